// round 2
// baseline (speedup 1.0000x reference)
#include <cuda_runtime.h>
#include <cuda_bf16.h>

// Problem constants (fixed by the reference: B=512, V=32768, C=16)
#define BB   512
#define VV   32768
#define CC   16
#define TPB  256
#define SPLIT 8
#define BPS  (BB / SPLIT)      // 64 samples per split
#define VBLOCKS (VV / TPB)     // 128 v-tiles

// Deterministic scratch: per-split partial sums [SPLIT][C][V] (16 MB) + counts.
__device__ float g_partial[(size_t)SPLIT * CC * VV];
__device__ int   g_counts[CC];
__device__ int   g_init[CC];

// ---------------------------------------------------------------------------
// Kernel 1: per-class counts + decode `initialized` (dtype-sniffed) (tiny)
// ---------------------------------------------------------------------------
__global__ void prep_kernel(const int* __restrict__ labels,
                            const unsigned char* __restrict__ initp) {
    __shared__ int cnt[CC];
    __shared__ int mode;  // 0=uint8, 1=int32, 2=float32
    if (threadIdx.x == 0) {
        bool i32like = true, f32like = true, anyNZ = false;
        for (int i = 0; i < 16; ++i) {
            if ((i & 3) != 0 && initp[i] != 0) i32like = false;
            if (initp[i] != 0) anyNZ = true;
        }
        const float* fp = (const float*)initp;
        for (int c = 0; c < 4; ++c) {
            float f = fp[c];
            if (!(f == 0.0f || f == 1.0f)) f32like = false;
        }
        if (!anyNZ)        mode = 0;   // all representations agree (zeros); safest
        else if (f32like)  mode = 2;   // requires 1.0f bit pattern -> unambiguous
        else if (i32like)  mode = 1;
        else               mode = 0;
    }
    if (threadIdx.x < CC) cnt[threadIdx.x] = 0;
    __syncthreads();
    if (threadIdx.x < CC) {
        int c = threadIdx.x, v;
        if (mode == 2)      v = (((const float*)initp)[c] != 0.0f);
        else if (mode == 1) v = (((const int*)initp)[c] != 0);
        else                v = (initp[c] != 0);
        g_init[c] = v;
    }
    for (int b = threadIdx.x; b < BB; b += blockDim.x)
        atomicAdd(&cnt[labels[b]], 1);
    __syncthreads();
    if (threadIdx.x < CC) g_counts[threadIdx.x] = cnt[threadIdx.x];
}

// ---------------------------------------------------------------------------
// Kernel 2: gather + |sv*w| + segment-sum into per-split partials.
// Grid: (VBLOCKS, SPLIT). Each thread owns one v column for 64 b's and
// accumulates into smem[class][tid] (conflict-free, race-free per column).
// ---------------------------------------------------------------------------
__global__ __launch_bounds__(TPB) void accum_kernel(
    const float* __restrict__ sv,
    const float* __restrict__ W,
    const int*   __restrict__ labels)
{
    __shared__ float acc[CC][TPB];
    __shared__ int   slab[BPS];

    const int tid   = threadIdx.x;
    const int v     = blockIdx.x * TPB + tid;
    const int split = blockIdx.y;
    const int b0    = split * BPS;

    if (tid < BPS) slab[tid] = labels[b0 + tid];
#pragma unroll
    for (int c = 0; c < CC; ++c) acc[c][tid] = 0.0f;
    __syncthreads();

    const float* svp = sv + (size_t)b0 * VV + v;
    const float* Wp  = W  + ((size_t)b0 * VV + v) * CC;

    // 8 b's per batch: 16 independent global loads in flight per thread.
#pragma unroll 1
    for (int bb = 0; bb < BPS; bb += 8) {
        int   l[8];
        float s[8];
        float w[8];
#pragma unroll
        for (int k = 0; k < 8; ++k) l[k] = slab[bb + k];
#pragma unroll
        for (int k = 0; k < 8; ++k)
            s[k] = __ldcs(svp + (size_t)(bb + k) * VV);
#pragma unroll
        for (int k = 0; k < 8; ++k)
            w[k] = __ldcs(Wp + (size_t)(bb + k) * VV * CC + l[k]);
#pragma unroll
        for (int k = 0; k < 8; ++k)
            acc[l[k]][tid] += fabsf(s[k] * w[k]);
    }

    // Write this split's partials (coalesced over tid; fully written -> no zeroing)
    float* outp = g_partial + ((size_t)split * CC) * VV + v;
#pragma unroll
    for (int c = 0; c < CC; ++c)
        outp[(size_t)c * VV] = acc[c][tid];
}

// ---------------------------------------------------------------------------
// Kernel 3: reduce splits, mean, EMA / copy / no-op, write [C,V]
// ---------------------------------------------------------------------------
__global__ __launch_bounds__(256) void finalize_kernel(
    const float* __restrict__ centroids,
    float*       __restrict__ out)
{
    const int idx = blockIdx.x * blockDim.x + threadIdx.x;  // over C*V
    const int c = idx >> 15;           // /V
    const int v = idx & (VV - 1);

    float s = 0.0f;
#pragma unroll
    for (int p = 0; p < SPLIT; ++p)
        s += g_partial[((size_t)p * CC + c) * VV + v];

    const int   cnt  = g_counts[c];
    const float mean = s / fmaxf((float)cnt, 1.0f);
    const float cent = centroids[idx];

    const float ALPHA = (float)(2.0 / 1001.0);  // 1 - MOMENTUM
    const float upd = g_init[c] ? (cent + ALPHA * (mean - cent)) : mean;
    out[idx] = (cnt > 0) ? upd : cent;
}

// ---------------------------------------------------------------------------
// Launch. Inputs are bound by UNIQUE element count (robust to metadata order):
//   sparse_vector f32 [B,V]     -> 16,777,216
//   W_eff         f32 [B,V,C]   -> 268,435,456
//   labels        i32 [B]       -> 512
//   centroids     f32 [C,V]     -> 524,288
//   initialized   bool[C]       -> 16
// output f32 [C,V]
// ---------------------------------------------------------------------------
extern "C" void kernel_launch(void* const* d_in, const int* in_sizes, int n_in,
                              void* d_out, int out_size)
{
    const float*         sv   = nullptr;
    const float*         W    = nullptr;
    const int*           lab  = nullptr;
    const float*         cent = nullptr;
    const unsigned char* init = nullptr;

    for (int i = 0; i < n_in; ++i) {
        long n = (long)in_sizes[i];
        if      (n == (long)BB * VV)       sv   = (const float*)d_in[i];
        else if (n == (long)BB * VV * CC)  W    = (const float*)d_in[i];
        else if (n == (long)BB)            lab  = (const int*)d_in[i];
        else if (n == (long)CC * VV)       cent = (const float*)d_in[i];
        else if (n == (long)CC)            init = (const unsigned char*)d_in[i];
    }
    // Fallback to positional binding if size matching somehow failed.
    if (!sv)   sv   = (const float*)d_in[0];
    if (!W)    W    = (const float*)d_in[1];
    if (!lab)  lab  = (const int*)d_in[2];
    if (!cent) cent = (const float*)d_in[3];
    if (!init) init = (const unsigned char*)d_in[4];

    float* out = (float*)d_out;

    prep_kernel<<<1, 256>>>(lab, init);
    accum_kernel<<<dim3(VBLOCKS, SPLIT), TPB>>>(sv, W, lab);
    finalize_kernel<<<(CC * VV) / 256, 256>>>(cent, out);
}